// round 9
// baseline (speedup 1.0000x reference)
#include <cuda_runtime.h>
#include <stdint.h>
#include <math.h>

#define BB 32
#define TT 256
#define INS 64
#define HH 128
#define G4 512
#define EPSV 1e-7f

typedef unsigned long long u64;
typedef unsigned int u32;

// ---- static device scratch (no cudaMalloc allowed) ----
__device__ __align__(16) u64 g_whp[32 * 512 * 2];   // W_hh packed: [k4][j] -> float4 as 2x u64
__device__ float g_gx[BB * TT * G4];                // precomputed input gate contributions

__device__ __forceinline__ u64 ffma2(u64 a, u64 b, u64 c) {
    u64 d;
    asm("fma.rn.f32x2 %0, %1, %2, %3;" : "=l"(d) : "l"(a), "l"(b), "l"(c));
    return d;
}
__device__ __forceinline__ float f2sum(u64 v) {
    float2 f = *reinterpret_cast<float2*>(&v);
    return f.x + f.y;
}
__device__ __forceinline__ float fsig(float x)  { return 1.0f / (1.0f + __expf(-x)); }
__device__ __forceinline__ float ftanh(float x) { return 2.0f / (1.0f + __expf(-2.0f * x)) - 1.0f; }

__device__ __forceinline__ u32 smem_u32(const void* p) {
    u32 a;
    asm("{ .reg .u64 t; cvta.to.shared.u64 t, %1; cvt.u32.u64 %0, t; }" : "=r"(a) : "l"(p));
    return a;
}

__device__ __forceinline__ void mbar_wait_cluster(u32 mb, u32 parity) {
    asm volatile(
        "{\n\t"
        ".reg .pred P;\n\t"
        "WL_%=:\n\t"
        "mbarrier.try_wait.parity.acquire.cluster.shared::cta.b64 P, [%0], %1, 0x989680;\n\t"
        "@P bra.uni WD_%=;\n\t"
        "bra.uni WL_%=;\n\t"
        "WD_%=:\n\t"
        "}"
        :: "r"(mb), "r"(parity) : "memory");
}

// ---------------- fused pack + gx kernel ----------------
__global__ __launch_bounds__(512) void gxpack_kernel(const float* __restrict__ x,
                                                     const float* __restrict__ W_ih,
                                                     const float* __restrict__ W_hh,
                                                     const float* __restrict__ b_ih,
                                                     const float* __restrict__ b_hh) {
    int b = blockIdx.x, ty = blockIdx.y, j = threadIdx.x;

    if (ty == 0) {
        float* whp = (float*)g_whp;
        for (int idx = b * 512 + j; idx < G4 * HH; idx += 32 * 512) {
            int r = idx >> 7, k = idx & 127;
            whp[((k >> 2) * 512 + r) * 4 + (k & 3)] = W_hh[idx];
        }
    }

    __shared__ float xs[16][INS];
    int t0 = ty * 16;
    for (int idx = j; idx < 16 * INS; idx += 512)
        xs[idx >> 6][idx & 63] = x[(b * TT + t0 + (idx >> 6)) * INS + (idx & 63)];

    float4 w[16];
    const float4* wr = (const float4*)(W_ih + j * INS);
#pragma unroll
    for (int k4 = 0; k4 < 16; k4++) w[k4] = wr[k4];
    float bs = b_ih[j] + b_hh[j];
    __syncthreads();

    for (int tt = 0; tt < 16; tt++) {
        float acc = bs;
#pragma unroll
        for (int k4 = 0; k4 < 16; k4++) {
            acc = fmaf(w[k4].x, xs[tt][4 * k4 + 0], acc);
            acc = fmaf(w[k4].y, xs[tt][4 * k4 + 1], acc);
            acc = fmaf(w[k4].z, xs[tt][4 * k4 + 2], acc);
            acc = fmaf(w[k4].w, xs[tt][4 * k4 + 3], acc);
        }
        g_gx[(b * TT + t0 + tt) * G4 + j] = acc;
    }
}

// ---------------- recurrent kernel ----------------
// Cluster of 2 CTAs per batch row; 544 threads each.
// Invariant: W.h = W.hl + sum_s u[s] * Wslot[s]; Wslot partials live in GEMV-thread
// registers and are updated incrementally on top-5 insertion (no extra GEMV ever).
// Attention (ac/hf/pbv) is OFF the recurrence critical path.
__global__ __launch_bounds__(544) void rec_kernel(const float* __restrict__ w_t,
                                                  float* __restrict__ out) {
    int tid = threadIdx.x, lane = tid & 31, wrp = tid >> 5;
    int b = blockIdx.x >> 1;

    u32 rank;
    asm("mov.u32 %0, %%cluster_ctarank;" : "=r"(rank));
    u32 peer = rank ^ 1u;

    __shared__ __align__(16) float h_sh[HH];       // holds hl each step
    __shared__ float gpart[2][2][G4];              // [parity][khalf][gate]
    __shared__ float pbv[HH];
    __shared__ float u_sh[5];                      // per-slot attention weights
    __shared__ float redA[4];
    __shared__ float sb_arr[8];
    __shared__ float top5v[5];
    __shared__ int   top5r[5];
    __shared__ int   top5s[5];
    __shared__ int   rowslot[5];
    __shared__ int   evslot;
    __shared__ float wa_s[HH], wb_s[HH];
    __shared__ __align__(8) u64 mbar[2];

    float* out_c = out;             // [B,H]
    float* out_w = out + BB * HH;   // [B,T]
    const float* gxb = g_gx + b * TT * G4;

    if (tid < HH) {
        h_sh[tid] = 0.0f;
        wa_s[tid] = w_t[tid];
        wb_s[tid] = w_t[HH + tid];
    }
    if (tid == 0) {
        sb_arr[0] = 0.0f;
        top5v[0] = 0.0f; top5r[0] = 0; top5s[0] = 0;
        for (int q = 1; q < 5; q++) { top5v[q] = -1e30f; top5r[q] = -1; top5s[q] = q; }
        rowslot[0] = 0;
        evslot = -1;
        for (int q = 0; q < 5; q++) u_sh[q] = 0.0f;
        asm volatile("mbarrier.init.shared.b64 [%0], 1;" :: "r"(smem_u32(&mbar[0])) : "memory");
        asm volatile("mbarrier.init.shared.b64 [%0], 1;" :: "r"(smem_u32(&mbar[1])) : "memory");
    }
    if (rank == 0 && tid < TT) out_w[b * TT + tid] = 0.0f;

    // cluster-space addresses
    u32 mb0 = smem_u32(&mbar[0]);
    u32 mb1 = smem_u32(&mbar[1]);
    u32 gl0 = smem_u32(&gpart[0][rank][0]);
    u32 gl1 = smem_u32(&gpart[1][rank][0]);
    u32 sl0, sl1, smb0, smb1, gr0, gr1, rmb0, rmb1;
    asm("mapa.shared::cluster.u32 %0, %1, %2;" : "=r"(sl0)  : "r"(gl0), "r"(rank));
    asm("mapa.shared::cluster.u32 %0, %1, %2;" : "=r"(sl1)  : "r"(gl1), "r"(rank));
    asm("mapa.shared::cluster.u32 %0, %1, %2;" : "=r"(smb0) : "r"(mb0), "r"(rank));
    asm("mapa.shared::cluster.u32 %0, %1, %2;" : "=r"(smb1) : "r"(mb1), "r"(rank));
    asm("mapa.shared::cluster.u32 %0, %1, %2;" : "=r"(gr0)  : "r"(gl0), "r"(peer));
    asm("mapa.shared::cluster.u32 %0, %1, %2;" : "=r"(gr1)  : "r"(gl1), "r"(peer));
    asm("mapa.shared::cluster.u32 %0, %1, %2;" : "=r"(rmb0) : "r"(mb0), "r"(peer));
    asm("mapa.shared::cluster.u32 %0, %1, %2;" : "=r"(rmb1) : "r"(mb1), "r"(peer));

    // persistent registers
    float c_reg = 0.0f, ac = 0.0f, hl = 0.0f, hf_prev = 0.0f;
    float sr0 = 0.f, sr1 = 0.f, sr2 = 0.f, sr3 = 0.f, sr4 = 0.f;   // slot h values (tail)
    float ws0 = 0.f, ws1 = 0.f, ws2 = 0.f, ws3 = 0.f, ws4 = 0.f;   // W.slot partials (GEMV)
    float partWh = 0.0f;                                            // W.h partial from prev step
    u32 ph0 = 0, ph1 = 0;

    ulonglong2 wc[16];
    float gxv = 0.0f;
    if (tid < 512) {
        const ulonglong2* wp = (const ulonglong2*)g_whp;
#pragma unroll
        for (int k4 = 0; k4 < 16; k4++) wc[k4] = wp[(rank * 16 + k4) * 512 + tid];
        if (rank == 0) gxv = gxb[tid];   // gx[0]
    }

    __syncthreads();
    asm volatile("barrier.cluster.arrive.aligned;" ::: "memory");
    asm volatile("barrier.cluster.wait.aligned;"   ::: "memory");

    // ---- prologue: deliver g_0 = Wx_0 partials into gpart[0] ----
    if (tid >= 512) {
        if (lane == 0)
            asm volatile("mbarrier.arrive.expect_tx.shared.b64 _, [%0], %1;"
                         :: "r"(mb0), "r"(4096u) : "memory");
    } else {
        float part0 = gxv;   // rank0: gx[0]; rank1: 0
        asm volatile("st.async.shared::cluster.mbarrier::complete_tx::bytes.f32 [%0], %1, [%2];"
                     :: "r"(sl0 + tid * 4u), "f"(part0), "r"(smb0) : "memory");
        asm volatile("st.async.shared::cluster.mbarrier::complete_tx::bytes.f32 [%0], %1, [%2];"
                     :: "r"(gr0 + tid * 4u), "f"(part0), "r"(rmb0) : "memory");
        if (rank == 0) gxv = gxb[G4 + tid];   // gx[1]
    }

    for (int i = 0; i < TT; i++) {
        int p = i & 1;

        if (tid >= 512) {
            // ---- scheduler warp: expect_tx for next buffer + top-5 + u weights ----
            if (lane == 0 && i + 1 < TT) {
                u32 mb = p ? mb0 : mb1;   // parity p^1
                asm volatile("mbarrier.arrive.expect_tx.shared.b64 _, [%0], %1;"
                             :: "r"(mb), "r"(4096u) : "memory");
            }
            if (i > 0) {
                float s = pbv[lane] + pbv[lane + 32] + pbv[lane + 64] + pbv[lane + 96];
#pragma unroll
                for (int o = 16; o; o >>= 1) s += __shfl_xor_sync(0xffffffffu, s, o);
                if (lane == 0) {
                    float sbn = s;
                    if (i < 5) sb_arr[i] = sbn;
                    if (sbn > top5v[4]) {
                        int evs = top5s[4];
                        int q = 4;
                        while (q > 0 && sbn > top5v[q - 1]) {
                            top5v[q] = top5v[q - 1]; top5r[q] = top5r[q - 1]; top5s[q] = top5s[q - 1];
                            q--;
                        }
                        top5v[q] = sbn; top5r[q] = i; top5s[q] = evs;
                        if (i < 5) rowslot[i] = evs;
                        evslot = evs;
                    } else evslot = -1;
                    if (i >= 5) {
                        // per-slot weights (ta cancels); top5s is a permutation of 0..4
                        float d = top5v[4] + EPSV;
                        float v0 = fmaxf(top5v[0] - d, 0.0f);
                        float v1 = fmaxf(top5v[1] - d, 0.0f);
                        float v2 = fmaxf(top5v[2] - d, 0.0f);
                        float v3 = fmaxf(top5v[3] - d, 0.0f);
                        float v4 = fmaxf(top5v[4] - d, 0.0f);
                        float inv = 1.0f / (v0 + v1 + v2 + v3 + v4 + EPSV);
                        u_sh[top5s[0]] = v0 * inv;
                        u_sh[top5s[1]] = v1 * inv;
                        u_sh[top5s[2]] = v2 * inv;
                        u_sh[top5s[3]] = v3 * inv;
                        u_sh[top5s[4]] = v4 * inv;
                    }
                }
            }
        } else if (tid < HH) {
            // ---- tail: wait g_i, gates, cell -> hl ----
            if (p) { mbar_wait_cluster(mb1, ph1); ph1 ^= 1u; }
            else   { mbar_wait_cluster(mb0, ph0); ph0 ^= 1u; }
            float ti = fsig (gpart[p][0][tid]          + gpart[p][1][tid]);
            float tf = fsig (gpart[p][0][HH + tid]     + gpart[p][1][HH + tid]);
            float tg = ftanh(gpart[p][0][2 * HH + tid] + gpart[p][1][2 * HH + tid]);
            float to = fsig (gpart[p][0][3 * HH + tid] + gpart[p][1][3 * HH + tid]);
            c_reg = tf * c_reg + ti * tg;
            hl = to * ftanh(c_reg);
            h_sh[tid] = hl;
        }
        __syncthreads();   // bar1: hl + (i>=5: u,evslot) ready

        if (i < 5) {
            // startup path: raw scores need ta = tanh(hl).wa
            if (tid < HH) {
                float pa = ftanh(hl) * wa_s[tid];
#pragma unroll
                for (int o = 16; o; o >>= 1) pa += __shfl_xor_sync(0xffffffffu, pa, o);
                if (lane == 0) redA[wrp] = pa;
                asm volatile("bar.sync 1, 128;" ::: "memory");
                if (tid == 0) {
                    float ta = redA[0] + redA[1] + redA[2] + redA[3];
                    float uu[5] = {0.f, 0.f, 0.f, 0.f, 0.f};
                    for (int r = 0; r <= i; r++) uu[rowslot[r]] += ta + sb_arr[r];
                    for (int q = 0; q < 5; q++) u_sh[q] = uu[q];
                }
            }
            __syncthreads();   // bar1b: u ready
        }

        if (tid < 512) {
            float u0 = u_sh[0], u1 = u_sh[1], u2 = u_sh[2], u3 = u_sh[3], u4 = u_sh[4];
            int ev = evslot;
            // insert W.h_{i-1} partial into evicted W-slot (register select)
            if (ev == 0) ws0 = partWh; else if (ev == 1) ws1 = partWh;
            else if (ev == 2) ws2 = partWh; else if (ev == 3) ws3 = partWh;
            else if (ev == 4) ws4 = partWh;

            if (i + 1 < TT) {
                // GEMV over hl (register weights)
                const ulonglong2* h2 = (const ulonglong2*)h_sh;
                u64 a0 = 0ull, a1 = 0ull, a2 = 0ull, a3 = 0ull;
#pragma unroll
                for (int k4 = 0; k4 < 16; k4++) {
                    ulonglong2 w = wc[k4];
                    ulonglong2 hv = h2[rank * 16 + k4];
                    if (k4 & 1) { a2 = ffma2(w.x, hv.x, a2); a3 = ffma2(w.y, hv.y, a3); }
                    else        { a0 = ffma2(w.x, hv.x, a0); a1 = ffma2(w.y, hv.y, a1); }
                }
                float whl = (f2sum(a0) + f2sum(a1)) + (f2sum(a2) + f2sum(a3));
                // W.h = W.hl + sum_s u[s]*Wslot[s]
                float pnw = whl;
                pnw = fmaf(u0, ws0, pnw); pnw = fmaf(u1, ws1, pnw);
                pnw = fmaf(u2, ws2, pnw); pnw = fmaf(u3, ws3, pnw);
                pnw = fmaf(u4, ws4, pnw);
                float part = pnw + gxv;   // gxv = 0 on rank 1

                u32 la = (p ? sl0 : sl1) + tid * 4u;   // parity p^1 buffers
                u32 lm = p ? smb0 : smb1;
                u32 ra = (p ? gr0 : gr1) + tid * 4u;
                u32 rm = p ? rmb0 : rmb1;
                asm volatile("st.async.shared::cluster.mbarrier::complete_tx::bytes.f32 [%0], %1, [%2];"
                             :: "r"(la), "f"(part), "r"(lm) : "memory");
                asm volatile("st.async.shared::cluster.mbarrier::complete_tx::bytes.f32 [%0], %1, [%2];"
                             :: "r"(ra), "f"(part), "r"(rm) : "memory");
                partWh = pnw;
                if (rank == 0 && i + 2 < TT) gxv = gxb[(i + 2) * G4 + tid];
            }

            if (tid < HH) {
                // attention combine (off critical path)
                if (ev == 0) sr0 = hf_prev; else if (ev == 1) sr1 = hf_prev;
                else if (ev == 2) sr2 = hf_prev; else if (ev == 3) sr3 = hf_prev;
                else if (ev == 4) sr4 = hf_prev;
                ac = u0 * sr0;
                ac = fmaf(u1, sr1, ac); ac = fmaf(u2, sr2, ac);
                ac = fmaf(u3, sr3, ac); ac = fmaf(u4, sr4, ac);
                float hf = hl + ac;
                hf_prev = hf;
                pbv[tid] = ftanh(hf) * wb_s[tid];
            }
        }
        __syncthreads();   // bar2: pbv/u/evslot stable for next step
    }

    // ---- epilogue (rank 0 only) ----
    if (rank == 0) {
        if (tid < HH) out_c[b * HH + tid] = ac;
        if (tid == 0) {
            float d = top5v[4] + EPSV;
            float ssum = 0.0f, v[5];
#pragma unroll
            for (int q = 0; q < 5; q++) { v[q] = fmaxf(top5v[q] - d, 0.0f); ssum += v[q]; }
            float inv = 1.0f / (ssum + EPSV);
#pragma unroll
            for (int q = 0; q < 5; q++)
                if (v[q] > 0.0f) out_w[b * TT + top5r[q]] = v[q] * inv;
        }
    }
    asm volatile("barrier.cluster.arrive.aligned;" ::: "memory");
    asm volatile("barrier.cluster.wait.aligned;"   ::: "memory");
}

extern "C" void kernel_launch(void* const* d_in, const int* in_sizes, int n_in,
                              void* d_out, int out_size) {
    const float* x    = (const float*)d_in[0];
    const float* W_ih = (const float*)d_in[1];
    const float* W_hh = (const float*)d_in[2];
    const float* b_ih = (const float*)d_in[3];
    const float* b_hh = (const float*)d_in[4];
    const float* w_t  = (const float*)d_in[5];
    float* out = (float*)d_out;

    gxpack_kernel<<<dim3(BB, TT / 16), 512>>>(x, W_ih, W_hh, b_ih, b_hh);

    cudaLaunchConfig_t cfg = {};
    cfg.gridDim  = dim3(2 * BB, 1, 1);
    cfg.blockDim = dim3(544, 1, 1);
    cfg.dynamicSmemBytes = 0;
    cfg.stream = 0;
    cudaLaunchAttribute attrs[1];
    attrs[0].id = cudaLaunchAttributeClusterDimension;
    attrs[0].val.clusterDim.x = 2;
    attrs[0].val.clusterDim.y = 1;
    attrs[0].val.clusterDim.z = 1;
    cfg.attrs = attrs;
    cfg.numAttrs = 1;
    cudaLaunchKernelEx(&cfg, rec_kernel, w_t, out);
}

// round 11
// speedup vs baseline: 1.3634x; 1.3634x over previous
#include <cuda_runtime.h>
#include <stdint.h>
#include <math.h>

#define BB 32
#define TT 256
#define INS 64
#define HH 128
#define G4 512
#define EPSV 1e-7f

typedef unsigned long long u64;
typedef unsigned int u32;

// ---- static device scratch (no cudaMalloc allowed) ----
__device__ __align__(16) u64 g_whp[32 * 512 * 2];   // W_hh packed: [k4][j] -> float4 as 2x u64
__device__ float g_gx[BB * TT * G4];                // precomputed input gate contributions

__device__ __forceinline__ u64 ffma2(u64 a, u64 b, u64 c) {
    u64 d;
    asm("fma.rn.f32x2 %0, %1, %2, %3;" : "=l"(d) : "l"(a), "l"(b), "l"(c));
    return d;
}
__device__ __forceinline__ float f2sum(u64 v) {
    float2 f = *reinterpret_cast<float2*>(&v);
    return f.x + f.y;
}
// accuracy-safe nonlinearities (tanh.approx fails the attn_w check: R10)
__device__ __forceinline__ float fsig(float x)  { return 1.0f / (1.0f + __expf(-x)); }
__device__ __forceinline__ float ftanh(float x) { return 2.0f / (1.0f + __expf(-2.0f * x)) - 1.0f; }

__device__ __forceinline__ u32 smem_u32(const void* p) {
    u32 a;
    asm("{ .reg .u64 t; cvta.to.shared.u64 t, %1; cvt.u32.u64 %0, t; }" : "=r"(a) : "l"(p));
    return a;
}

// CTA-scope acquire: tx-completion already made peer bytes visible in local SMEM.
__device__ __forceinline__ void mbar_wait(u32 mb, u32 parity) {
    asm volatile(
        "{\n\t"
        ".reg .pred P;\n\t"
        "WL_%=:\n\t"
        "mbarrier.try_wait.parity.acquire.cta.shared::cta.b64 P, [%0], %1, 0x989680;\n\t"
        "@P bra.uni WD_%=;\n\t"
        "bra.uni WL_%=;\n\t"
        "WD_%=:\n\t"
        "}"
        :: "r"(mb), "r"(parity) : "memory");
}

// ---------------- fused pack + gx kernel ----------------
__global__ __launch_bounds__(512) void gxpack_kernel(const float* __restrict__ x,
                                                     const float* __restrict__ W_ih,
                                                     const float* __restrict__ W_hh,
                                                     const float* __restrict__ b_ih,
                                                     const float* __restrict__ b_hh) {
    int b = blockIdx.x, ty = blockIdx.y, j = threadIdx.x;

    if (ty == 0) {
        float* whp = (float*)g_whp;
        for (int idx = b * 512 + j; idx < G4 * HH; idx += 32 * 512) {
            int r = idx >> 7, k = idx & 127;
            whp[((k >> 2) * 512 + r) * 4 + (k & 3)] = W_hh[idx];
        }
    }

    __shared__ float xs[16][INS];
    int t0 = ty * 16;
    for (int idx = j; idx < 16 * INS; idx += 512)
        xs[idx >> 6][idx & 63] = x[(b * TT + t0 + (idx >> 6)) * INS + (idx & 63)];

    float4 w[16];
    const float4* wr = (const float4*)(W_ih + j * INS);
#pragma unroll
    for (int k4 = 0; k4 < 16; k4++) w[k4] = wr[k4];
    float bs = b_ih[j] + b_hh[j];
    __syncthreads();

    for (int tt = 0; tt < 16; tt++) {
        float acc = bs;
#pragma unroll
        for (int k4 = 0; k4 < 16; k4++) {
            acc = fmaf(w[k4].x, xs[tt][4 * k4 + 0], acc);
            acc = fmaf(w[k4].y, xs[tt][4 * k4 + 1], acc);
            acc = fmaf(w[k4].z, xs[tt][4 * k4 + 2], acc);
            acc = fmaf(w[k4].w, xs[tt][4 * k4 + 3], acc);
        }
        g_gx[(b * TT + t0 + tt) * G4 + j] = acc;
    }
}

// ---------------- recurrent kernel: cluster of 2 CTAs per batch row ----------------
// (R8 skeleton) 544 threads: warps 0-15 GEMV k-half (register weights, rank0 folds gx);
// warp 16 = scheduler (top-5 + expect_tx). Partials delivered local+peer via st.async,
// tx-counted on one mbarrier per parity. Wait is CTA-scope acquire.
__global__ __launch_bounds__(544) void rec_kernel(const float* __restrict__ w_t,
                                                  float* __restrict__ out) {
    int tid = threadIdx.x, lane = tid & 31, wrp = tid >> 5;
    int b = blockIdx.x >> 1;

    u32 rank;
    asm("mov.u32 %0, %%cluster_ctarank;" : "=r"(rank));
    u32 peer = rank ^ 1u;

    __shared__ __align__(16) float h_sh[HH];
    __shared__ float gpart[2][2][G4];              // [parity][khalf][gate]
    __shared__ float pbv[HH];
    __shared__ __align__(16) float slots[5][HH];
    __shared__ float redA[4];
    __shared__ float sb_arr[8];
    __shared__ float top5v[5];
    __shared__ int   top5r[5];
    __shared__ int   top5s[5];
    __shared__ int   rowslot[5];
    __shared__ int   evslot;
    __shared__ float wa_s[HH], wb_s[HH];
    __shared__ __align__(8) u64 mbar[2];

    float* out_c = out;             // [B,H]
    float* out_w = out + BB * HH;   // [B,T]
    const float* gxb = g_gx + b * TT * G4;

    if (tid < HH) {
        h_sh[tid] = 0.0f;
        slots[0][tid] = 0.0f;
        wa_s[tid] = w_t[tid];
        wb_s[tid] = w_t[HH + tid];
    }
    if (tid == 0) {
        sb_arr[0] = 0.0f;
        top5v[0] = 0.0f; top5r[0] = 0; top5s[0] = 0;
        for (int q = 1; q < 5; q++) { top5v[q] = -1e30f; top5r[q] = -1; top5s[q] = q; }
        rowslot[0] = 0;
        evslot = -1;
        asm volatile("mbarrier.init.shared.b64 [%0], 1;" :: "r"(smem_u32(&mbar[0])) : "memory");
        asm volatile("mbarrier.init.shared.b64 [%0], 1;" :: "r"(smem_u32(&mbar[1])) : "memory");
    }
    if (rank == 0 && tid < TT) out_w[b * TT + tid] = 0.0f;

    // cluster-space addresses: own buffers (for local st.async) + peer buffers
    u32 mb0 = smem_u32(&mbar[0]);
    u32 mb1 = smem_u32(&mbar[1]);
    u32 gl0 = smem_u32(&gpart[0][rank][0]);
    u32 gl1 = smem_u32(&gpart[1][rank][0]);
    u32 sl0, sl1, smb0, smb1, gr0, gr1, rmb0, rmb1;
    asm("mapa.shared::cluster.u32 %0, %1, %2;" : "=r"(sl0)  : "r"(gl0), "r"(rank));
    asm("mapa.shared::cluster.u32 %0, %1, %2;" : "=r"(sl1)  : "r"(gl1), "r"(rank));
    asm("mapa.shared::cluster.u32 %0, %1, %2;" : "=r"(smb0) : "r"(mb0), "r"(rank));
    asm("mapa.shared::cluster.u32 %0, %1, %2;" : "=r"(smb1) : "r"(mb1), "r"(rank));
    asm("mapa.shared::cluster.u32 %0, %1, %2;" : "=r"(gr0)  : "r"(gl0), "r"(peer));
    asm("mapa.shared::cluster.u32 %0, %1, %2;" : "=r"(gr1)  : "r"(gl1), "r"(peer));
    asm("mapa.shared::cluster.u32 %0, %1, %2;" : "=r"(rmb0) : "r"(mb0), "r"(peer));
    asm("mapa.shared::cluster.u32 %0, %1, %2;" : "=r"(rmb1) : "r"(mb1), "r"(peer));

    float c_reg = 0.0f;
    float ac = 0.0f;
    u32 ph0 = 0, ph1 = 0;

    ulonglong2 wc[16];
    float gxv = 0.0f;
    if (tid < 512) {
        const ulonglong2* wp = (const ulonglong2*)g_whp;
#pragma unroll
        for (int k4 = 0; k4 < 16; k4++) wc[k4] = wp[(rank * 16 + k4) * 512 + tid];
        if (rank == 0) gxv = gxb[tid];   // gx folded into rank-0 partial
    }

    __syncthreads();
    asm volatile("barrier.cluster.arrive.aligned;" ::: "memory");
    asm volatile("barrier.cluster.wait.aligned;"   ::: "memory");

    for (int i = 0; i < TT; i++) {
        int p = i & 1;

        if (tid < 512) {
            // ---- GEMV half (register weights); rank 0 adds gx ----
            const ulonglong2* h2 = (const ulonglong2*)h_sh;
            u64 a0 = 0ull, a1 = 0ull, a2 = 0ull, a3 = 0ull;
#pragma unroll
            for (int k4 = 0; k4 < 16; k4++) {
                ulonglong2 w = wc[k4];
                ulonglong2 hv = h2[rank * 16 + k4];
                if (k4 & 1) { a2 = ffma2(w.x, hv.x, a2); a3 = ffma2(w.y, hv.y, a3); }
                else        { a0 = ffma2(w.x, hv.x, a0); a1 = ffma2(w.y, hv.y, a1); }
            }
            float part = gxv + (f2sum(a0) + f2sum(a1)) + (f2sum(a2) + f2sum(a3));
            if (rank == 0 && i + 1 < TT) gxv = gxb[(i + 1) * G4 + tid];  // prefetch

            // local + remote delivery, both tx-counted on destination CTA's mbar[p]
            u32 la = (p ? sl1 : sl0) + tid * 4u;
            u32 lm = p ? smb1 : smb0;
            u32 ra = (p ? gr1 : gr0) + tid * 4u;
            u32 rm = p ? rmb1 : rmb0;
            asm volatile("st.async.shared::cluster.mbarrier::complete_tx::bytes.f32 [%0], %1, [%2];"
                         :: "r"(la), "f"(part), "r"(lm) : "memory");
            asm volatile("st.async.shared::cluster.mbarrier::complete_tx::bytes.f32 [%0], %1, [%2];"
                         :: "r"(ra), "f"(part), "r"(rm) : "memory");

            if (tid < HH) {
                // overlap DSMEM RTT: sync with scheduler warp, insert evicted slot
                asm volatile("bar.sync 2, 160;" ::: "memory");
                int ev = evslot;
                if (ev >= 0) slots[ev][tid] = h_sh[tid];   // row i = h(i-1)

                // wait for all 4096 bytes of partials (CTA-scope acquire)
                if (p) { mbar_wait(mb1, ph1); ph1 ^= 1u; }
                else   { mbar_wait(mb0, ph0); ph0 ^= 1u; }

                // gates
                float ti = fsig (gpart[p][0][tid]          + gpart[p][1][tid]);
                float tf = fsig (gpart[p][0][HH + tid]     + gpart[p][1][HH + tid]);
                float tg = ftanh(gpart[p][0][2 * HH + tid] + gpart[p][1][2 * HH + tid]);
                float to = fsig (gpart[p][0][3 * HH + tid] + gpart[p][1][3 * HH + tid]);
                c_reg = tf * c_reg + ti * tg;
                float hl = to * ftanh(c_reg);

                float wv[5]; int ws[5];
                if (i < 5) {
                    // ta needed only while rem<=5 (raw unnormalized scores)
                    float pa = ftanh(hl) * wa_s[tid];
#pragma unroll
                    for (int o = 16; o; o >>= 1) pa += __shfl_xor_sync(0xffffffffu, pa, o);
                    if (lane == 0) redA[wrp] = pa;
                    asm volatile("bar.sync 1, 128;" ::: "memory");
                    float ta = redA[0] + redA[1] + redA[2] + redA[3];
                    int rem = i + 1;
#pragma unroll
                    for (int r = 0; r < 5; r++) {
                        if (r < rem) { wv[r] = ta + sb_arr[r]; ws[r] = rowslot[r]; }
                        else         { wv[r] = 0.0f;           ws[r] = 0; }
                    }
                } else {
                    // ta cancels in the clipped-sparse path
                    float d = top5v[4] + EPSV;
                    float ssum = 0.0f;
#pragma unroll
                    for (int q = 0; q < 5; q++) {
                        float v = fmaxf(top5v[q] - d, 0.0f);
                        wv[q] = v; ws[q] = top5s[q];
                        ssum += v;
                    }
                    float inv = 1.0f / (ssum + EPSV);
#pragma unroll
                    for (int q = 0; q < 5; q++) wv[q] *= inv;
                }
                ac = 0.0f;
#pragma unroll
                for (int q = 0; q < 5; q++) ac = fmaf(wv[q], slots[ws[q]][tid], ac);
                float hf = hl + ac;
                h_sh[tid] = hf;
                pbv[tid] = ftanh(hf) * wb_s[tid];   // reduced by warp 16 next step
            }
        } else {
            // ---- warp 16: expect_tx + top-5 maintenance (overlaps GEMV) ----
            if (lane == 0) {
                u32 mb = p ? mb1 : mb0;
                asm volatile("mbarrier.arrive.expect_tx.shared.b64 _, [%0], %1;"
                             :: "r"(mb), "r"(4096u) : "memory");
            }
            if (i > 0) {
                float s = pbv[lane] + pbv[lane + 32] + pbv[lane + 64] + pbv[lane + 96];
#pragma unroll
                for (int o = 16; o; o >>= 1) s += __shfl_xor_sync(0xffffffffu, s, o);
                if (lane == 0) {
                    float sbn = s;
                    if (i < 5) sb_arr[i] = sbn;
                    if (sbn > top5v[4]) {
                        int evs = top5s[4];
                        int q = 4;
                        while (q > 0 && sbn > top5v[q - 1]) {
                            top5v[q] = top5v[q - 1]; top5r[q] = top5r[q - 1]; top5s[q] = top5s[q - 1];
                            q--;
                        }
                        top5v[q] = sbn; top5r[q] = i; top5s[q] = evs;
                        if (i < 5) rowslot[i] = evs;
                        evslot = evs;
                    } else evslot = -1;
                }
            }
            asm volatile("bar.sync 2, 160;" ::: "memory");
        }
        __syncthreads();  // step boundary: h_sh/pbv stable for next step
    }

    // ---- epilogue (rank 0 only) ----
    if (rank == 0) {
        if (tid < HH) out_c[b * HH + tid] = ac;
        if (tid == 0) {
            float d = top5v[4] + EPSV;
            float ssum = 0.0f, v[5];
#pragma unroll
            for (int q = 0; q < 5; q++) { v[q] = fmaxf(top5v[q] - d, 0.0f); ssum += v[q]; }
            float inv = 1.0f / (ssum + EPSV);
#pragma unroll
            for (int q = 0; q < 5; q++)
                if (v[q] > 0.0f) out_w[b * TT + top5r[q]] = v[q] * inv;
        }
    }
    asm volatile("barrier.cluster.arrive.aligned;" ::: "memory");
    asm volatile("barrier.cluster.wait.aligned;"   ::: "memory");
}

extern "C" void kernel_launch(void* const* d_in, const int* in_sizes, int n_in,
                              void* d_out, int out_size) {
    const float* x    = (const float*)d_in[0];
    const float* W_ih = (const float*)d_in[1];
    const float* W_hh = (const float*)d_in[2];
    const float* b_ih = (const float*)d_in[3];
    const float* b_hh = (const float*)d_in[4];
    const float* w_t  = (const float*)d_in[5];
    float* out = (float*)d_out;

    gxpack_kernel<<<dim3(BB, TT / 16), 512>>>(x, W_ih, W_hh, b_ih, b_hh);

    cudaLaunchConfig_t cfg = {};
    cfg.gridDim  = dim3(2 * BB, 1, 1);
    cfg.blockDim = dim3(544, 1, 1);
    cfg.dynamicSmemBytes = 0;
    cfg.stream = 0;
    cudaLaunchAttribute attrs[1];
    attrs[0].id = cudaLaunchAttributeClusterDimension;
    attrs[0].val.clusterDim.x = 2;
    attrs[0].val.clusterDim.y = 1;
    attrs[0].val.clusterDim.z = 1;
    cfg.attrs = attrs;
    cfg.numAttrs = 1;
    cudaLaunchKernelEx(&cfg, rec_kernel, w_t, out);
}